// round 2
// baseline (speedup 1.0000x reference)
#include <cuda_runtime.h>
#include <cuda_bf16.h>

// Problem constants: shape (2,3,512,512) fp32, KS=5, PAD=2, ALPHA1=0.1, ALPHA2=1.5, EPS=1e-8
#define HH 512
#define WW 512
#define NPLANE 6
#define NPIX (HH * WW)
#define NTOT (NPLANE * NPIX)          // 1,572,864 per tensor

#define GX 16                          // 512/32
#define GY 64                          // 512/8
#define NBLOCKS (GX * GY * NPLANE)     // 6144

__device__ int   g_negflag[2];
__device__ float g_partials[NBLOCKS];

// ---------------------------------------------------------------------------
// raw ex2.approx (the __expf building block, without the log2e FMUL -- we fold
// log2e into the precomputed constants)
__device__ __forceinline__ float ex2f(float x) {
    float y;
    asm("ex2.approx.ftz.f32 %0, %1;" : "=f"(y) : "f"(x));
    return y;
}

__device__ __forceinline__ int reflect(int i) {
    // jnp.pad mode='reflect', pad=2, dim=512:  -1->1, -2->2, 512->510, 513->509
    return (i < 0) ? -i : ((i >= HH) ? (2 * HH - 2 - i) : i);
}

// ---------------------------------------------------------------------------
__global__ void zero_flags_kernel() {
    g_negflag[0] = 0;
    g_negflag[1] = 0;
}

// "img.min() < 0"  <=>  any element < 0  -> one cheap flag pass per tensor
__global__ __launch_bounds__(256) void flag_kernel(const float4* __restrict__ a,
                                                   const float4* __restrict__ b,
                                                   int n4) {
    int fa = 0, fb = 0;
    for (int i = blockIdx.x * blockDim.x + threadIdx.x; i < n4;
         i += gridDim.x * blockDim.x) {
        float4 va = a[i];
        float4 vb = b[i];
        fa |= (va.x < 0.f) | (va.y < 0.f) | (va.z < 0.f) | (va.w < 0.f);
        fb |= (vb.x < 0.f) | (vb.y < 0.f) | (vb.z < 0.f) | (vb.w < 0.f);
    }
    // warp-collective: one store per warp that saw a negative (benign: only 0->1)
    if (__any_sync(0xffffffffu, fa) && ((threadIdx.x & 31) == 0)) g_negflag[0] = 1;
    if (__any_sync(0xffffffffu, fb) && ((threadIdx.x & 31) == 0)) g_negflag[1] = 1;
}

// ---------------------------------------------------------------------------
// Fused bilateral(output), bilateral(target), |diff| partial-sum per block.
// Block = 32x8 output pixels; smem tile (32+4)x(8+4) per tensor.
__global__ __launch_bounds__(256) void bilat_kernel(const float* __restrict__ A,
                                                    const float* __restrict__ B) {
    __shared__ float sA[12][36];
    __shared__ float sB[12][36];
    __shared__ float swarp[8];

    const int tx  = threadIdx.x;           // 0..31
    const int ty  = threadIdx.y;           // 0..7
    const int tid = ty * 32 + tx;
    const int x0  = blockIdx.x * 32;
    const int y0  = blockIdx.y * 8;
    const int plane = blockIdx.z;

    const float sclA = g_negflag[0] ? 0.5f : 1.0f;
    const float bseA = g_negflag[0] ? 0.5f : 0.0f;
    const float sclB = g_negflag[1] ? 0.5f : 1.0f;
    const float bseB = g_negflag[1] ? 0.5f : 0.0f;

    const float* __restrict__ Ap = A + plane * NPIX;
    const float* __restrict__ Bp = B + plane * NPIX;

    // cooperative halo load (reflect at borders), normalized at load time
#pragma unroll
    for (int idx = tid; idx < 12 * 36; idx += 256) {
        int r  = idx / 36;
        int c  = idx - r * 36;
        int gy = reflect(y0 - 2 + r);
        int gx = reflect(x0 - 2 + c);
        int g  = gy * WW + gx;
        sA[r][c] = fmaf(__ldg(Ap + g), sclA, bseA);
        sB[r][c] = fmaf(__ldg(Bp + g), sclB, bseB);
    }
    __syncthreads();

    const float ca = sA[ty + 2][tx + 2];
    const float cb = sB[ty + 2][tx + 2];

    float wsA = 0.f, acA = 0.f, wsB = 0.f, acB = 0.f;

    const float L2E  = 1.4426950408889634f;
    const float NEGK = -5.0f * L2E;        // -(1/(2*alpha1)) * log2(e)

#pragma unroll
    for (int dy = 0; dy < 5; dy++) {
#pragma unroll
        for (int dx = 0; dx < 5; dx++) {
            // spatial term folded into the exponent (log2 domain), compile-time const
            const float off = (float)((dy - 2) * (dy - 2) + (dx - 2) * (dx - 2))
                              * (L2E / 3.0f);   // (gx^2+gy^2)/(2*alpha2) * log2e

            float pa = sA[ty + dy][tx + dx];
            float da = pa - ca;
            float wa = ex2f(fmaf(da * da, NEGK, -off));
            wsA += wa;
            acA  = fmaf(wa, pa, acA);

            float pb = sB[ty + dy][tx + dx];
            float db = pb - cb;
            float wb = ex2f(fmaf(db * db, NEGK, -off));
            wsB += wb;
            acB  = fmaf(wb, pb, acB);
        }
    }

    float fa = __fdividef(acA, wsA + 1e-8f);
    float fb = __fdividef(acB, wsB + 1e-8f);
    float v  = fabsf(fa - fb);

    // deterministic block reduction
#pragma unroll
    for (int o = 16; o > 0; o >>= 1) v += __shfl_down_sync(0xffffffffu, v, o);
    if ((tid & 31) == 0) swarp[tid >> 5] = v;
    __syncthreads();
    if (tid < 8) {
        float t = swarp[tid];
#pragma unroll
        for (int o = 4; o > 0; o >>= 1) t += __shfl_down_sync(0x000000ffu, t, o);
        if (tid == 0) {
            int bidx = (blockIdx.z * gridDim.y + blockIdx.y) * gridDim.x + blockIdx.x;
            g_partials[bidx] = t;
        }
    }
}

// ---------------------------------------------------------------------------
__global__ __launch_bounds__(256) void final_reduce_kernel(float* __restrict__ out) {
    __shared__ float swarp[8];
    float s = 0.f;
    for (int i = threadIdx.x; i < NBLOCKS; i += 256) s += g_partials[i];
#pragma unroll
    for (int o = 16; o > 0; o >>= 1) s += __shfl_down_sync(0xffffffffu, s, o);
    if ((threadIdx.x & 31) == 0) swarp[threadIdx.x >> 5] = s;
    __syncthreads();
    if (threadIdx.x < 8) {
        float t = swarp[threadIdx.x];
#pragma unroll
        for (int o = 4; o > 0; o >>= 1) t += __shfl_down_sync(0x000000ffu, t, o);
        if (threadIdx.x == 0) out[0] = t * (1.0f / (float)NTOT);
    }
}

// ---------------------------------------------------------------------------
extern "C" void kernel_launch(void* const* d_in, const int* in_sizes, int n_in,
                              void* d_out, int out_size) {
    const float* A = (const float*)d_in[0];   // output
    const float* B = (const float*)d_in[1];   // target
    float* out = (float*)d_out;

    zero_flags_kernel<<<1, 1>>>();
    flag_kernel<<<256, 256>>>((const float4*)A, (const float4*)B, NTOT / 4);

    dim3 grid(GX, GY, NPLANE);
    dim3 block(32, 8);
    bilat_kernel<<<grid, block>>>(A, B);

    final_reduce_kernel<<<1, 256>>>(out);
}